// round 9
// baseline (speedup 1.0000x reference)
#include <cuda_runtime.h>
#include <math.h>

// Problem constants (fixed by the dataset)
#define BATCH   512
#define IN_DIM  128
#define OUT_DIM 128
#define NFEAT   9                  // silu + 8 basis functions
#define IPB     16                 // input dims per block (k-split granularity)
#define KC      (IPB * NFEAT)      // 144 k per block
#define SPLITS  (IN_DIM / IPB)     // 8 k-splits
#define CHI     8                  // i's per smem chunk
#define CHK     (CHI * NFEAT)      // 72 k per chunk
#define BM      64                 // batch rows per block
#define BO      64                 // out cols per block
#define MT      (BATCH / BM)       // 8 m-tiles
#define OT      (OUT_DIM / BO)     // 2 o-tiles
#define NBLK    (MT * OT * SPLITS) // 128 blocks (single wave on 148 SMs)
#define NTHR    512
#define FS2_STR 66                 // Fs2 row stride in 8-byte entries
#define WS_STR  68                 // Ws row stride in floats (16B multiple)
#define NOUT    (BATCH * OUT_DIM)  // 65536

// Scratch (device globals — no allocation in kernel_launch)
__device__ float        g_P[SPLITS * NOUT];  // split-K partials (2.1 MB)
__device__ unsigned int g_bar;               // monotonic barrier ticket counter

// ---------------------------------------------------------------------------
// f32x2 packed helpers (sm_103a FFMA2 — ptxas never emits this from C++)
// ---------------------------------------------------------------------------
__device__ __forceinline__ unsigned long long dup_f32x2(float v) {
    unsigned long long d;
    unsigned int u = __float_as_uint(v);
    asm("mov.b64 %0, {%1, %1};" : "=l"(d) : "r"(u));
    return d;
}
__device__ __forceinline__ void ffma2(unsigned long long& acc,
                                      unsigned long long a,
                                      unsigned long long b) {
    asm("fma.rn.f32x2 %0, %1, %2, %0;" : "+l"(acc) : "l"(a), "l"(b));
}

// ---------------------------------------------------------------------------
// Single persistent kernel, 512 threads, 128 blocks (single wave):
//   phase 1 (x2 chunks): build Fs2 (pre-dup f32x2) + Ws in smem, f32x2 GEMM
//   grid barrier (monotonic ticket; replay-safe)
//   phase 2: reduce L2-warm partials (8-way) -> out
// grid = (8 m, 2 o, 8 ksplit).
// ---------------------------------------------------------------------------
__global__ void __launch_bounds__(NTHR, 1)
fused_kernel(const float* __restrict__ x,
             const float* __restrict__ grid,
             const float* __restrict__ coef,
             const float* __restrict__ sb,
             const float* __restrict__ ss,
             const float* __restrict__ mask,
             float* __restrict__ out) {
    __shared__ unsigned long long Fs2[CHK * FS2_STR]; // 38.0 KB, [k][m] dup'd
    __shared__ float              Ws [CHK * WS_STR];  // 19.6 KB, [k][o]

    const int t  = threadIdx.x;
    const int m0 = blockIdx.x * BM;
    const int o0 = blockIdx.y * BO;
    const int i0 = blockIdx.z * IPB;

    // ---- uniform extended knot vector (division-free) ----
    const float g0 = grid[0];
    const float g5 = grid[5];
    const float step = (g5 - g0) * 0.2f;
    const float inv1 = __frcp_rn(step);
    const float invr[3] = { inv1, 0.5f * inv1, inv1 * (1.0f / 3.0f) };

    float tk[12];
    tk[0]  = g0 - step * 3.0f;
    tk[1]  = g0 - step * 2.0f;
    tk[2]  = g0 - step;
    tk[3]  = g0;
    tk[4]  = grid[1];
    tk[5]  = grid[2];
    tk[6]  = grid[3];
    tk[7]  = grid[4];
    tk[8]  = g5;
    tk[9]  = g5 + step;
    tk[10] = g5 + step * 2.0f;
    tk[11] = g5 + step * 3.0f;

    // GEMM lane mapping: warp=(wm 0..3, wo 0..3); lane=(lm 0..7, lo 0..3).
    // f: 128B contiguous per warp; w: 64B (8-lane broadcast groups).
    const int lane = t & 31;
    const int warp = t >> 5;
    const int mOff = (warp & 3) * 16 + (lane >> 2) * 2;   // Fs2 entry index
    const int oOff = (warp >> 2) * 16 + (lane & 3) * 4;   // Ws float index

    unsigned long long acc00 = 0ULL, acc01 = 0ULL;
    unsigned long long acc10 = 0ULL, acc11 = 0ULL;

#pragma unroll 1
    for (int c = 0; c < KC / CHK; c++) {
        const int ic = i0 + c * CHI;

        // ---- Fs2 build: 64 n x 8 i = 512 x-values, 1 per thread ----
        {
            const int il = t & 7;
            const int nl = t >> 3;
            const float xv = __ldg(&x[(m0 + nl) * IN_DIM + ic + il]);

            const float sig  = __frcp_rn(1.0f + __expf(-xv));
            const float silu = xv * sig;

            float B[11];
#pragma unroll
            for (int m = 0; m < 11; m++)
                B[m] = (xv >= tk[m] && xv < tk[m + 1]) ? 1.0f : 0.0f;
#pragma unroll
            for (int r = 1; r <= 3; r++) {
                const float iv = invr[r - 1];
#pragma unroll
                for (int m = 0; m < 11 - r; m++) {
                    float alpha = (xv - tk[m]) * iv;
                    float beta  = (tk[m + r + 1] - xv) * iv;
                    B[m] = alpha * B[m] + beta * B[m + 1];
                }
            }

            const int kb = il * NFEAT;
            Fs2[kb * FS2_STR + nl] = dup_f32x2(silu);
#pragma unroll
            for (int j = 0; j < 8; j++)
                Fs2[(kb + 1 + j) * FS2_STR + nl] = dup_f32x2(B[j]);
        }

        // ---- Ws build: 64 o x 8 i = 512 (o,i) pairs, 1 per thread ----
        {
            const int o = t >> 3;
            const int i = t & 7;
            const int s = (o0 + o) * IN_DIM + ic + i;

            const float4 c0 = __ldg((const float4*)&coef[s * 8]);
            const float4 c1 = __ldg((const float4*)&coef[s * 8 + 4]);
            const float mk  = __ldg(&mask[s]);
            const float wb  = mk * __ldg(&sb[s]);
            const float ws  = mk * __ldg(&ss[s]);

            const int kb = i * NFEAT;
            Ws[kb * WS_STR + o]       = wb;
            Ws[(kb + 1) * WS_STR + o] = ws * c0.x;
            Ws[(kb + 2) * WS_STR + o] = ws * c0.y;
            Ws[(kb + 3) * WS_STR + o] = ws * c0.z;
            Ws[(kb + 4) * WS_STR + o] = ws * c0.w;
            Ws[(kb + 5) * WS_STR + o] = ws * c1.x;
            Ws[(kb + 6) * WS_STR + o] = ws * c1.y;
            Ws[(kb + 7) * WS_STR + o] = ws * c1.z;
            Ws[(kb + 8) * WS_STR + o] = ws * c1.w;
        }

        __syncthreads();

        // ---- GEMM chunk: 2m x 4o per thread, packed f32x2 ----
#pragma unroll 8
        for (int k = 0; k < CHK; k++) {
            const ulonglong2 f = *(const ulonglong2*)&Fs2[k * FS2_STR + mOff];
            const ulonglong2 w = *(const ulonglong2*)&Ws[k * WS_STR + oOff];

            ffma2(acc00, f.x, w.x); ffma2(acc01, f.x, w.y);
            ffma2(acc10, f.y, w.x); ffma2(acc11, f.y, w.y);
        }

        __syncthreads();
    }

    // ---- store partials ----
    {
        float* P = &g_P[blockIdx.z * NOUT];
        const int row = m0 + mOff;           // mOff entries == m rows
        const int col = o0 + oOff;
        ulonglong2 v0; v0.x = acc00; v0.y = acc01;
        ulonglong2 v1; v1.x = acc10; v1.y = acc11;
        *(ulonglong2*)&P[row * OUT_DIM + col]       = v0;
        *(ulonglong2*)&P[(row + 1) * OUT_DIM + col] = v1;
    }

    // ---- grid barrier (monotonic ticket; works across graph replays) ----
    __threadfence();
    __syncthreads();
    __shared__ unsigned int s_target;
    if (t == 0) {
        unsigned int ticket = atomicAdd(&g_bar, 1u);
        s_target = ticket - (ticket & (NBLK - 1)) + NBLK;  // epoch base + 128
    }
    __syncthreads();
    if (t == 0) {
        const unsigned int target = s_target;
        while (*(volatile unsigned int*)&g_bar < target) { }
    }
    __syncthreads();
    __threadfence();

    // ---- phase 2: reduce L2-warm partials, 1 output per thread ----
    {
        const int flat = blockIdx.x + MT * (blockIdx.y + OT * blockIdx.z);
        const int idx  = flat * NTHR + t;                // 0..65535
        float v[SPLITS];
#pragma unroll
        for (int q = 0; q < SPLITS; q++)
            v[q] = g_P[q * NOUT + idx];
        float s = 0.0f;
#pragma unroll
        for (int q = 0; q < SPLITS; q++)
            s += v[q];
        out[idx] = s;
    }
}

// ---------------------------------------------------------------------------
extern "C" void kernel_launch(void* const* d_in, const int* in_sizes, int n_in,
                              void* d_out, int out_size) {
    const float* x    = (const float*)d_in[0];
    const float* grid = (const float*)d_in[1];
    const float* coef = (const float*)d_in[2];
    const float* sb   = (const float*)d_in[3];
    const float* ss   = (const float*)d_in[4];
    const float* mask = (const float*)d_in[5];
    float* out = (float*)d_out;

    fused_kernel<<<dim3(MT, OT, SPLITS), NTHR>>>(x, grid, coef, sb, ss, mask, out);
}

// round 10
// speedup vs baseline: 1.6923x; 1.6923x over previous
#include <cuda_runtime.h>
#include <math.h>

// Problem constants (fixed by the dataset)
#define BATCH   512
#define IN_DIM  128
#define OUT_DIM 128
#define NFEAT   9                  // silu + 8 basis functions
#define IPB     8                  // input dims per block (k-split granularity)
#define KC      (IPB * NFEAT)      // 72 k per block
#define SPLITS  (IN_DIM / IPB)     // 16 k-splits
#define BM      64                 // batch rows per block
#define MT      (BATCH / BM)       // 8 m-tiles
#define NBLK    (MT * SPLITS)      // 128 blocks (single wave on 148 SMs)
#define NTHR    512
#define FS2_STR 66                 // Fs2 row stride in 8-byte entries (even)
#define WS_STR  132                // Ws row stride in floats (16B multiple)
#define NOUT    (BATCH * OUT_DIM)  // 65536

// Scratch (device globals — no allocation in kernel_launch)
__device__ float        g_P[SPLITS * NOUT];  // split-K partials (4.2 MB)
__device__ unsigned int g_bar;               // monotonic barrier ticket counter

// ---------------------------------------------------------------------------
// f32x2 packed helpers (sm_103a FFMA2 — ptxas never emits this from C++)
// ---------------------------------------------------------------------------
__device__ __forceinline__ unsigned long long dup_f32x2(float v) {
    unsigned long long d;
    unsigned int u = __float_as_uint(v);
    asm("mov.b64 %0, {%1, %1};" : "=l"(d) : "r"(u));
    return d;
}
__device__ __forceinline__ void ffma2(unsigned long long& acc,
                                      unsigned long long a,
                                      unsigned long long b) {
    asm("fma.rn.f32x2 %0, %1, %2, %0;" : "+l"(acc) : "l"(a), "l"(b));
}

// ---------------------------------------------------------------------------
// Single persistent kernel, 512 threads, 128 blocks (single wave):
//   phase 1: build Fs2 (pre-dup f32x2 features) + Ws in smem,
//            f32x2 GEMM (4m x 4o per thread) with explicit software
//            pipelining (prefetch k+1 operands before k's FFMA2 block)
//   grid barrier (monotonic ticket; replay-safe)
//   phase 2: reduce L2-warm partials -> out
// ---------------------------------------------------------------------------
__global__ void __launch_bounds__(NTHR, 1)
fused_kernel(const float* __restrict__ x,
             const float* __restrict__ grid,
             const float* __restrict__ coef,
             const float* __restrict__ sb,
             const float* __restrict__ ss,
             const float* __restrict__ mask,
             float* __restrict__ out) {
    __shared__ unsigned long long Fs2[KC * FS2_STR]; // 38.0 KB, [k][m] dup'd
    __shared__ float              Ws [KC * WS_STR];  // 38.0 KB, [k][o]

    const int t  = threadIdx.x;
    const int m0 = blockIdx.x * BM;
    const int i0 = blockIdx.y * IPB;

    // ---- uniform extended knot vector (division-free) ----
    const float g0 = grid[0];
    const float g5 = grid[5];
    const float step = (g5 - g0) * 0.2f;
    const float inv1 = __frcp_rn(step);
    const float invr[3] = { inv1, 0.5f * inv1, inv1 * (1.0f / 3.0f) };

    float tk[12];
    tk[0]  = g0 - step * 3.0f;
    tk[1]  = g0 - step * 2.0f;
    tk[2]  = g0 - step;
    tk[3]  = g0;
    tk[4]  = grid[1];
    tk[5]  = grid[2];
    tk[6]  = grid[3];
    tk[7]  = grid[4];
    tk[8]  = g5;
    tk[9]  = g5 + step;
    tk[10] = g5 + step * 2.0f;
    tk[11] = g5 + step * 3.0f;

    // ---- Fs2 build: 64 n x 8 i = 512 x-values, 1 per thread ----
    {
        const int il = t & 7;
        const int nl = t >> 3;
        const float xv = __ldg(&x[(m0 + nl) * IN_DIM + i0 + il]);

        const float sig  = __frcp_rn(1.0f + __expf(-xv));
        const float silu = xv * sig;

        float B[11];
#pragma unroll
        for (int m = 0; m < 11; m++)
            B[m] = (xv >= tk[m] && xv < tk[m + 1]) ? 1.0f : 0.0f;
#pragma unroll
        for (int r = 1; r <= 3; r++) {
            const float iv = invr[r - 1];
#pragma unroll
            for (int m = 0; m < 11 - r; m++) {
                float alpha = (xv - tk[m]) * iv;
                float beta  = (tk[m + r + 1] - xv) * iv;
                B[m] = alpha * B[m] + beta * B[m + 1];
            }
        }

        const int kb = il * NFEAT;
        Fs2[kb * FS2_STR + nl] = dup_f32x2(silu);
#pragma unroll
        for (int j = 0; j < 8; j++)
            Fs2[(kb + 1 + j) * FS2_STR + nl] = dup_f32x2(B[j]);
    }

    // ---- Ws build: 128 o x 8 i = 1024 (o,i) pairs, 2 per thread ----
#pragma unroll
    for (int q = 0; q < 2; q++) {
        const int p = t + NTHR * q;
        const int o = p >> 3;
        const int i = p & 7;
        const int s = o * IN_DIM + i0 + i;

        const float4 c0 = __ldg((const float4*)&coef[s * 8]);
        const float4 c1 = __ldg((const float4*)&coef[s * 8 + 4]);
        const float mk  = __ldg(&mask[s]);
        const float wb  = mk * __ldg(&sb[s]);
        const float ws  = mk * __ldg(&ss[s]);

        const int kb = i * NFEAT;
        Ws[kb * WS_STR + o]       = wb;
        Ws[(kb + 1) * WS_STR + o] = ws * c0.x;
        Ws[(kb + 2) * WS_STR + o] = ws * c0.y;
        Ws[(kb + 3) * WS_STR + o] = ws * c0.z;
        Ws[(kb + 4) * WS_STR + o] = ws * c0.w;
        Ws[(kb + 5) * WS_STR + o] = ws * c1.x;
        Ws[(kb + 6) * WS_STR + o] = ws * c1.y;
        Ws[(kb + 7) * WS_STR + o] = ws * c1.z;
        Ws[(kb + 8) * WS_STR + o] = ws * c1.w;
    }

    __syncthreads();

    // ---- GEMM: 4m x 4o per thread, packed f32x2, software-pipelined ----
    // warp = (wm 0..3, wo 0..3); lane = (lm 0..3, lo 0..7).
    // fA/fB: 4 unique 16B addrs (64B) per warp -> 1 wavefront each.
    // w:     8 unique 16B addrs (128B) per warp -> 1 wavefront.
    const int lane = t & 31;
    const int warp = t >> 5;
    const int mOff = (warp & 3) * 16 + (lane >> 3) * 4;  // Fs2 entry index
    const int oOff = (warp >> 2) * 32 + (lane & 7) * 4;  // Ws float index

    unsigned long long acc[4][2];
#pragma unroll
    for (int a = 0; a < 4; a++) { acc[a][0] = 0ULL; acc[a][1] = 0ULL; }

    const unsigned long long* fPtr = &Fs2[mOff];
    const float*              wPtr = &Ws[oOff];

    // prologue: load k = 0
    ulonglong2 fA = *(const ulonglong2*)(fPtr);
    ulonglong2 fB = *(const ulonglong2*)(fPtr + 2);
    ulonglong2 w  = *(const ulonglong2*)(wPtr);

#pragma unroll 8
    for (int k = 0; k < KC - 1; k++) {
        // prefetch k+1 BEFORE consuming k (covers LDS latency)
        const ulonglong2 fA1 = *(const ulonglong2*)(fPtr + (k + 1) * FS2_STR);
        const ulonglong2 fB1 = *(const ulonglong2*)(fPtr + (k + 1) * FS2_STR + 2);
        const ulonglong2 w1  = *(const ulonglong2*)(wPtr + (k + 1) * WS_STR);

        ffma2(acc[0][0], fA.x, w.x); ffma2(acc[0][1], fA.x, w.y);
        ffma2(acc[1][0], fA.y, w.x); ffma2(acc[1][1], fA.y, w.y);
        ffma2(acc[2][0], fB.x, w.x); ffma2(acc[2][1], fB.x, w.y);
        ffma2(acc[3][0], fB.y, w.x); ffma2(acc[3][1], fB.y, w.y);

        fA = fA1; fB = fB1; w = w1;
    }
    // epilogue: k = KC-1
    ffma2(acc[0][0], fA.x, w.x); ffma2(acc[0][1], fA.x, w.y);
    ffma2(acc[1][0], fA.y, w.x); ffma2(acc[1][1], fA.y, w.y);
    ffma2(acc[2][0], fB.x, w.x); ffma2(acc[2][1], fB.x, w.y);
    ffma2(acc[3][0], fB.y, w.x); ffma2(acc[3][1], fB.y, w.y);

    // ---- store partials ----
    {
        float* P = &g_P[blockIdx.y * NOUT];
#pragma unroll
        for (int a = 0; a < 4; a++) {
            const int row = m0 + mOff + a;
            ulonglong2 v; v.x = acc[a][0]; v.y = acc[a][1];
            *(ulonglong2*)&P[row * OUT_DIM + oOff] = v;
        }
    }

    // ---- grid barrier (monotonic ticket; works across graph replays) ----
    __threadfence();
    __syncthreads();
    __shared__ unsigned int s_target;
    if (t == 0) {
        unsigned int ticket = atomicAdd(&g_bar, 1u);
        s_target = ticket - (ticket & (NBLK - 1)) + NBLK;  // epoch base + 128
    }
    __syncthreads();
    if (t == 0) {
        const unsigned int target = s_target;
        while (*(volatile unsigned int*)&g_bar < target) { }
    }
    __syncthreads();
    __threadfence();

    // ---- phase 2: reduce L2-warm partials, 1 output per thread ----
    {
        const int flat = blockIdx.y * MT + blockIdx.x;   // 0..127
        const int idx  = flat * NTHR + t;                // 0..65535
        float v[SPLITS];
#pragma unroll
        for (int q = 0; q < SPLITS; q++)
            v[q] = g_P[q * NOUT + idx];
        float s = 0.0f;
#pragma unroll
        for (int q = 0; q < SPLITS; q++)
            s += v[q];
        out[idx] = s;
    }
}

// ---------------------------------------------------------------------------
extern "C" void kernel_launch(void* const* d_in, const int* in_sizes, int n_in,
                              void* d_out, int out_size) {
    const float* x    = (const float*)d_in[0];
    const float* grid = (const float*)d_in[1];
    const float* coef = (const float*)d_in[2];
    const float* sb   = (const float*)d_in[3];
    const float* ss   = (const float*)d_in[4];
    const float* mask = (const float*)d_in[5];
    float* out = (float*)d_out;

    fused_kernel<<<dim3(MT, SPLITS), NTHR>>>(x, grid, coef, sb, ss, mask, out);
}

// round 12
// speedup vs baseline: 1.9850x; 1.1729x over previous
#include <cuda_runtime.h>
#include <cuda_bf16.h>
#include <math.h>
#include <stdint.h>

// Problem constants (fixed by the dataset)
#define BATCH   512
#define IN_DIM  128
#define OUT_DIM 128
#define NFEAT   9                   // silu + 8 basis functions
#define IPB     4                   // input dims per block (k-split)
#define KPAD    48                  // 4 i * 12 padded cols (3 x k16 chunks)
#define SPLITS  (IN_DIM / IPB)      // 32 k-splits
#define BM      128                 // batch rows per block
#define MT      (BATCH / BM)        // 4 m-tiles
#define NBLK    (MT * SPLITS)       // 128 blocks (single wave on 148 SMs)
#define NTHR    512
#define NOUT    (BATCH * OUT_DIM)   // 65536
#define TSTR    56                  // smem row stride in bf16 (112B: conflict-free)
#define TILE_B  (128 * TSTR * 2)    // one tile: 14336 bytes
#define SMEM_BYTES (4 * TILE_B)     // 57344 bytes dynamic smem

// Scratch (device globals — no allocation in kernel_launch)
__device__ float        g_P[SPLITS * NOUT];  // split-K partials (8.4 MB)
__device__ unsigned int g_bar;               // monotonic barrier ticket counter

// ---------------------------------------------------------------------------
// HMMA m16n8k16 bf16 -> f32 (generic PTX, sm_80+; legal on sm_103 target)
// ---------------------------------------------------------------------------
__device__ __forceinline__ void mma_bf16(float* c, const uint32_t* a,
                                         const uint32_t* b) {
    asm volatile(
        "mma.sync.aligned.m16n8k16.row.col.f32.bf16.bf16.f32 "
        "{%0,%1,%2,%3}, {%4,%5,%6,%7}, {%8,%9}, {%0,%1,%2,%3};\n"
        : "+f"(c[0]), "+f"(c[1]), "+f"(c[2]), "+f"(c[3])
        : "r"(a[0]), "r"(a[1]), "r"(a[2]), "r"(a[3]),
          "r"(b[0]), "r"(b[1]));
}

// ---------------------------------------------------------------------------
// Single persistent kernel, 512 threads, 128 blocks (single wave):
//   phase 1: build bf16 hi/lo operand tiles in smem, HMMA GEMM
//            (D = Ah*Bh + Ah*Bl + Al*Bh, fp32 accum) -> split-K partials
//   grid barrier (monotonic ticket; replay-safe)
//   phase 2: reduce L2-warm partials -> out
// grid = (4 m-tiles, 32 k-splits)
// ---------------------------------------------------------------------------
__global__ void __launch_bounds__(NTHR, 1)
fused_kernel(const float* __restrict__ x,
             const float* __restrict__ grid,
             const float* __restrict__ coef,
             const float* __restrict__ sb,
             const float* __restrict__ ss,
             const float* __restrict__ mask,
             float* __restrict__ out) {
    extern __shared__ __nv_bfloat16 sm[];
    __nv_bfloat16* Ah = sm;                       // [128][TSTR]
    __nv_bfloat16* Al = sm + 128 * TSTR;
    __nv_bfloat16* Bh = sm + 2 * 128 * TSTR;
    __nv_bfloat16* Bl = sm + 3 * 128 * TSTR;
    __shared__ unsigned int s_target;

    const int t    = threadIdx.x;
    const int warp = t >> 5;
    const int lane = t & 31;
    const int m0   = blockIdx.x * BM;
    const int i0   = blockIdx.y * IPB;

    // zero all tiles (pad k-cols 9..11 per i must be 0)
#pragma unroll
    for (int q = 0; q < (SMEM_BYTES / 4) / NTHR; q++)
        ((uint32_t*)sm)[t + NTHR * q] = 0u;
    __syncthreads();

    // ---- uniform extended knot vector (division-free) ----
    const float g0 = grid[0];
    const float g5 = grid[5];
    const float step = (g5 - g0) * 0.2f;
    const float inv1 = __frcp_rn(step);
    const float invr[3] = { inv1, 0.5f * inv1, inv1 * (1.0f / 3.0f) };

    float tk[12];
    tk[0]  = g0 - step * 3.0f;
    tk[1]  = g0 - step * 2.0f;
    tk[2]  = g0 - step;
    tk[3]  = g0;
    tk[4]  = grid[1];
    tk[5]  = grid[2];
    tk[6]  = grid[3];
    tk[7]  = grid[4];
    tk[8]  = g5;
    tk[9]  = g5 + step;
    tk[10] = g5 + step * 2.0f;
    tk[11] = g5 + step * 3.0f;

    // ---- A build: 128 n x 4 i = 512 x-values, 1 per thread ----
    {
        const int n  = t >> 2;
        const int i  = t & 3;
        const float xv = __ldg(&x[(m0 + n) * IN_DIM + i0 + i]);

        const float sig = __frcp_rn(1.0f + __expf(-xv));
        float f[NFEAT];
        f[0] = xv * sig;                      // silu

        float B[11];
#pragma unroll
        for (int m = 0; m < 11; m++)
            B[m] = (xv >= tk[m] && xv < tk[m + 1]) ? 1.0f : 0.0f;
#pragma unroll
        for (int r = 1; r <= 3; r++) {
            const float iv = invr[r - 1];
#pragma unroll
            for (int m = 0; m < 11 - r; m++) {
                float alpha = (xv - tk[m]) * iv;
                float beta  = (tk[m + r + 1] - xv) * iv;
                B[m] = alpha * B[m] + beta * B[m + 1];
            }
        }
#pragma unroll
        for (int j = 0; j < 8; j++) f[1 + j] = B[j];

#pragma unroll
        for (int j = 0; j < NFEAT; j++) {
            const int off = n * TSTR + i * 12 + j;
            const __nv_bfloat16 h = __float2bfloat16(f[j]);
            const __nv_bfloat16 l = __float2bfloat16(f[j] - __bfloat162float(h));
            Ah[off] = h;
            Al[off] = l;
        }
    }

    // ---- B build: 128 o x 4 i = 512 (o,i) pairs, 1 per thread ----
    {
        const int o = t >> 2;
        const int i = t & 3;
        const int s = o * IN_DIM + i0 + i;

        const float4 c0 = __ldg((const float4*)&coef[s * 8]);
        const float4 c1 = __ldg((const float4*)&coef[s * 8 + 4]);
        const float mk  = __ldg(&mask[s]);
        const float ws  = mk * __ldg(&ss[s]);

        float w[NFEAT];
        w[0] = mk * __ldg(&sb[s]);
        w[1] = ws * c0.x; w[2] = ws * c0.y; w[3] = ws * c0.z; w[4] = ws * c0.w;
        w[5] = ws * c1.x; w[6] = ws * c1.y; w[7] = ws * c1.z; w[8] = ws * c1.w;

#pragma unroll
        for (int j = 0; j < NFEAT; j++) {
            const int off = o * TSTR + i * 12 + j;
            const __nv_bfloat16 h = __float2bfloat16(w[j]);
            const __nv_bfloat16 l = __float2bfloat16(w[j] - __bfloat162float(h));
            Bh[off] = h;
            Bl[off] = l;
        }
    }

    __syncthreads();

    // ---- HMMA GEMM ----
    // warp = (wm 0..7, wn 0..1): rows wm*16..+16, cols wn*64..+64 (8 n8 tiles)
    // frag coords: qr = lane>>2 (row/col group), qc = (lane&3)*2 (k pair)
    const int wm = warp & 7;
    const int wn = warp >> 3;
    const int qr = lane >> 2;
    const int qc = (lane & 3) * 2;

    // A fragments: [kc][hi/lo][4 regs]
    uint32_t afrag[3][2][4];
#pragma unroll
    for (int kc = 0; kc < 3; kc++) {
        const int r0 = (wm * 16 + qr) * TSTR + kc * 16 + qc;
        const int r8 = r0 + 8 * TSTR;
        afrag[kc][0][0] = *(const uint32_t*)&Ah[r0];
        afrag[kc][0][1] = *(const uint32_t*)&Ah[r8];
        afrag[kc][0][2] = *(const uint32_t*)&Ah[r0 + 8];
        afrag[kc][0][3] = *(const uint32_t*)&Ah[r8 + 8];
        afrag[kc][1][0] = *(const uint32_t*)&Al[r0];
        afrag[kc][1][1] = *(const uint32_t*)&Al[r8];
        afrag[kc][1][2] = *(const uint32_t*)&Al[r0 + 8];
        afrag[kc][1][3] = *(const uint32_t*)&Al[r8 + 8];
    }

    float* P = &g_P[blockIdx.y * NOUT];

#pragma unroll
    for (int nt = 0; nt < 8; nt++) {
        const int nb = wn * 64 + nt * 8;     // n-tile column base

        // B fragments: [kc][hi/lo][2 regs]
        uint32_t bfrag[3][2][2];
#pragma unroll
        for (int kc = 0; kc < 3; kc++) {
            const int b0 = (nb + qr) * TSTR + kc * 16 + qc;
            bfrag[kc][0][0] = *(const uint32_t*)&Bh[b0];
            bfrag[kc][0][1] = *(const uint32_t*)&Bh[b0 + 8];
            bfrag[kc][1][0] = *(const uint32_t*)&Bl[b0];
            bfrag[kc][1][1] = *(const uint32_t*)&Bl[b0 + 8];
        }

        float acc[4] = {0.f, 0.f, 0.f, 0.f};
#pragma unroll
        for (int kc = 0; kc < 3; kc++) {
            mma_bf16(acc, afrag[kc][0], bfrag[kc][0]);  // Ah*Bh
            mma_bf16(acc, afrag[kc][0], bfrag[kc][1]);  // Ah*Bl
            mma_bf16(acc, afrag[kc][1], bfrag[kc][0]);  // Al*Bh
        }

        // store D fragment to partials
        const int row = m0 + wm * 16 + qr;
        const int col = nb + qc;
        *(float2*)&P[row * OUT_DIM + col]       = make_float2(acc[0], acc[1]);
        *(float2*)&P[(row + 8) * OUT_DIM + col] = make_float2(acc[2], acc[3]);
    }

    // ---- grid barrier (monotonic ticket; works across graph replays) ----
    __threadfence();
    __syncthreads();
    if (t == 0) {
        unsigned int ticket = atomicAdd(&g_bar, 1u);
        s_target = ticket - (ticket & (NBLK - 1)) + NBLK;  // epoch base + 128
    }
    __syncthreads();
    if (t == 0) {
        const unsigned int target = s_target;
        while (*(volatile unsigned int*)&g_bar < target) { }
    }
    __syncthreads();
    __threadfence();

    // ---- phase 2: reduce L2-warm partials, 1 output per thread ----
    {
        const int flat = blockIdx.y * MT + blockIdx.x;   // 0..127
        const int idx  = flat * NTHR + t;                // 0..65535
        float s = 0.0f;
#pragma unroll
        for (int h = 0; h < 2; h++) {
            float v[16];
#pragma unroll
            for (int q = 0; q < 16; q++)
                v[q] = g_P[(h * 16 + q) * NOUT + idx];
#pragma unroll
            for (int q = 0; q < 16; q++)
                s += v[q];
        }
        out[idx] = s;
    }
}

// ---------------------------------------------------------------------------
extern "C" void kernel_launch(void* const* d_in, const int* in_sizes, int n_in,
                              void* d_out, int out_size) {
    const float* x    = (const float*)d_in[0];
    const float* grid = (const float*)d_in[1];
    const float* coef = (const float*)d_in[2];
    const float* sb   = (const float*)d_in[3];
    const float* ss   = (const float*)d_in[4];
    const float* mask = (const float*)d_in[5];
    float* out = (float*)d_out;

    cudaFuncSetAttribute(fused_kernel,
                         cudaFuncAttributeMaxDynamicSharedMemorySize,
                         SMEM_BYTES);
    fused_kernel<<<dim3(MT, SPLITS), NTHR, SMEM_BYTES>>>(
        x, grid, coef, sb, ss, mask, out);
}